// round 1
// baseline (speedup 1.0000x reference)
#include <cuda_runtime.h>
#include <math.h>

#define BB 8
#define LL 2048
#define DD 512
#define HH 1024
#define CC 64
#define MM (BB*LL)   // 16384

// ---------------- scratch (static device globals; no allocations) ----------------
__device__ float g_x  [MM*DD];   // residual stream           32 MB
__device__ float g_xn [MM*DD];   // LN output                 32 MB
__device__ float g_h  [MM*HH];   // MLP hidden                64 MB
__device__ float g_abc[MM*192];  // tanh projections a|b|c    12.6 MB
__device__ float g_u  [MM*192];  // ua|ub|uc                  12.6 MB
__device__ float g_qn [BB*DD];   // LN of last token

// ---------------- embedding: x = tok_emb[ids] + pos_emb ----------------
__global__ void embed_kernel(const int* __restrict__ ids,
                             const float* __restrict__ tok,
                             const float* __restrict__ pos,
                             float* __restrict__ x) {
    int t  = blockIdx.x;                 // 0..16383
    int id = ids[t];
    int l  = t & (LL - 1);
    float4 a = ((const float4*)(tok + (size_t)id * DD))[threadIdx.x];
    float4 p = ((const float4*)(pos + (size_t)l  * DD))[threadIdx.x];
    float4 o; o.x = a.x + p.x; o.y = a.y + p.y; o.z = a.z + p.z; o.w = a.w + p.w;
    ((float4*)(x + (size_t)t * DD))[threadIdx.x] = o;
}

// ---------------- LayerNorm over D=512, one block (128 thr) per row ----------------
// input row index = blockIdx.x * rowMul + rowOff ; output row index = blockIdx.x
__global__ void ln_kernel(const float* __restrict__ x,
                          const float* __restrict__ w,
                          const float* __restrict__ b,
                          float* __restrict__ out,
                          int rowMul, int rowOff) {
    __shared__ float red[2][4];
    size_t inRow = (size_t)blockIdx.x * rowMul + rowOff;
    float4 v = ((const float4*)(x + inRow * DD))[threadIdx.x];
    float s  = v.x + v.y + v.z + v.w;
    float s2 = v.x*v.x + v.y*v.y + v.z*v.z + v.w*v.w;
    #pragma unroll
    for (int o = 16; o; o >>= 1) {
        s  += __shfl_down_sync(0xffffffffu, s,  o);
        s2 += __shfl_down_sync(0xffffffffu, s2, o);
    }
    int warp = threadIdx.x >> 5, lane = threadIdx.x & 31;
    if (!lane) { red[0][warp] = s; red[1][warp] = s2; }
    __syncthreads();
    s  = red[0][0] + red[0][1] + red[0][2] + red[0][3];
    s2 = red[1][0] + red[1][1] + red[1][2] + red[1][3];
    float mean = s * (1.0f / DD);
    float var  = s2 * (1.0f / DD) - mean * mean;
    float inv  = rsqrtf(var + 1e-5f);
    int c = threadIdx.x * 4;
    float4 wv = *(const float4*)(w + c);
    float4 bv = *(const float4*)(b + c);
    float4 o;
    o.x = (v.x - mean) * inv * wv.x + bv.x;
    o.y = (v.y - mean) * inv * wv.y + bv.y;
    o.z = (v.z - mean) * inv * wv.z + bv.z;
    o.w = (v.w - mean) * inv * wv.w + bv.w;
    ((float4*)(out + (size_t)blockIdx.x * DD))[threadIdx.x] = o;
}

// ---------------- tiled SGEMM, C[M,N] (+epilogue) = A[M,K] @ B[K,N] ----------------
// EPI: 0 plain store, 1 bias+exact GELU, 2 bias + residual accumulate into C, 3 tanh
template<int BM, int BN, int BK, int TM, int TN, int EPI>
__global__ __launch_bounds__((BM/TM)*(BN/TN))
void sgemm_kernel(const float* __restrict__ A, const float* __restrict__ Bw,
                  const float* __restrict__ bias, float* __restrict__ Cm,
                  int M, int N, int K, int ldc, int colOff) {
    constexpr int NT = (BM/TM) * (BN/TN);
    constexpr int AP = BM + 4;                       // pad to soften store conflicts
    __shared__ float As[BK][AP];
    __shared__ float Bs[BK][BN];
    const int tid = threadIdx.x;
    const int tx  = tid % (BN/TN);
    const int ty  = tid / (BN/TN);
    const int rowBase = blockIdx.y * BM;
    const int colBase = blockIdx.x * BN;

    float acc[TM][TN];
    #pragma unroll
    for (int i = 0; i < TM; i++)
        #pragma unroll
        for (int j = 0; j < TN; j++) acc[i][j] = 0.f;

    constexpr int A_IT = (BM*BK/4) / NT;
    constexpr int B_IT = (BK*BN/4) / NT;

    for (int k0 = 0; k0 < K; k0 += BK) {
        #pragma unroll
        for (int it = 0; it < A_IT; it++) {
            int idx = tid + it * NT;
            int r = idx / (BK/4);
            int c = (idx % (BK/4)) * 4;
            float4 v = *(const float4*)(A + (size_t)(rowBase + r) * K + k0 + c);
            As[c+0][r] = v.x; As[c+1][r] = v.y; As[c+2][r] = v.z; As[c+3][r] = v.w;
        }
        #pragma unroll
        for (int it = 0; it < B_IT; it++) {
            int idx = tid + it * NT;
            int r = idx / (BN/4);
            int c = (idx % (BN/4)) * 4;
            *(float4*)&Bs[r][c] = *(const float4*)(Bw + (size_t)(k0 + r) * N + colBase + c);
        }
        __syncthreads();
        #pragma unroll
        for (int k = 0; k < BK; k++) {
            float af[TM], bf[TN];
            #pragma unroll
            for (int i = 0; i < TM; i += 4)
                *(float4*)&af[i] = *(const float4*)&As[k][ty*TM + i];
            #pragma unroll
            for (int j = 0; j < TN; j += 4)
                *(float4*)&bf[j] = *(const float4*)&Bs[k][tx*TN + j];
            #pragma unroll
            for (int i = 0; i < TM; i++)
                #pragma unroll
                for (int j = 0; j < TN; j++)
                    acc[i][j] = fmaf(af[i], bf[j], acc[i][j]);
        }
        __syncthreads();
    }

    #pragma unroll
    for (int i = 0; i < TM; i++) {
        int row = rowBase + ty*TM + i;
        #pragma unroll
        for (int j = 0; j < TN; j++) {
            int col = colBase + tx*TN + j;
            float v = acc[i][j];
            size_t idx = (size_t)row * ldc + colOff + col;
            if (EPI == 0) {
                Cm[idx] = v;
            } else if (EPI == 1) {           // bias + exact GELU
                v += bias[col];
                Cm[idx] = v * normcdff(v);
            } else if (EPI == 2) {           // bias + residual add
                v += bias[col];
                Cm[idx] += v;
            } else {                          // tanh
                Cm[idx] = tanhf(v);
            }
        }
    }
}

// ---------------- u[t, g*64+c] = sum_r abc[t, g*64+r] * class_g[c, r] ----------------
__global__ void u_kernel(const float* __restrict__ abc,
                         const float* __restrict__ cA,
                         const float* __restrict__ cB,
                         const float* __restrict__ cC,
                         float* __restrict__ u) {
    int g = blockIdx.y;
    const float* cls = (g == 0) ? cA : (g == 1) ? cB : cC;
    __shared__ float Ct[64][65];
    __shared__ float At[64][65];
    int tid = threadIdx.x;
    int t0  = blockIdx.x * 64;
    for (int i = tid; i < 4096; i += 256) Ct[i >> 6][i & 63] = cls[i];
    for (int i = tid; i < 4096; i += 256) {
        int tok = i >> 6, r = i & 63;
        At[tok][r] = abc[(size_t)(t0 + tok) * 192 + g * 64 + r];
    }
    __syncthreads();
    int tx = tid & 15, ty = tid >> 4;
    float acc[4][4];
    #pragma unroll
    for (int i = 0; i < 4; i++)
        #pragma unroll
        for (int j = 0; j < 4; j++) acc[i][j] = 0.f;
    for (int r = 0; r < 64; r++) {
        float a[4], b[4];
        #pragma unroll
        for (int i = 0; i < 4; i++) a[i] = At[ty*4 + i][r];
        #pragma unroll
        for (int j = 0; j < 4; j++) b[j] = Ct[tx*4 + j][r];
        #pragma unroll
        for (int i = 0; i < 4; i++)
            #pragma unroll
            for (int j = 0; j < 4; j++) acc[i][j] = fmaf(a[i], b[j], acc[i][j]);
    }
    #pragma unroll
    for (int i = 0; i < 4; i++)
        #pragma unroll
        for (int j = 0; j < 4; j++)
            u[(size_t)(t0 + ty*4 + i) * 192 + g * 64 + tx*4 + j] = acc[i][j];
}

// ---------------- sequential triplet scan + query head ----------------
__global__ void scan_kernel(const float* __restrict__ u,
                            const float* __restrict__ qn,
                            const float* __restrict__ Wq,
                            const float* __restrict__ bq,
                            float* __restrict__ out) {
    int b = blockIdx.x;        // 0..7
    int c = threadIdx.x;       // 0..63
    const float* base = u + (size_t)b * LL * 192;
    float prefA = 0.f, prefT = 0.f, s = 0.f;
    #pragma unroll 4
    for (int l = 0; l < LL - 1; l++) {
        const float* p = base + (size_t)l * 192;
        float va = p[c], vb = p[64 + c], vc = p[128 + c];
        s     = fmaf(vc, prefT, s);
        prefT = fmaf(vb, prefA, prefT);
        prefA += va;
    }
    float q = 0.f;
    const float* qr = qn + b * DD;
    #pragma unroll 8
    for (int k = 0; k < DD; k++) q = fmaf(qr[k], Wq[k * CC + c], q);
    const float inv_den = (float)(6.0 / (2047.0 * 2046.0 * 2045.0));
    out[b * CC + c] = s * inv_den + q + bq[c];
}

// ---------------- launch ----------------
extern "C" void kernel_launch(void* const* d_in, const int* in_sizes, int n_in,
                              void* d_out, int out_size) {
    const int*   ids       = (const int*)  d_in[0];
    const float* tok_emb   = (const float*)d_in[1];
    const float* pos_emb   = (const float*)d_in[2];
    const float* stem_ln_w = (const float*)d_in[3];
    const float* stem_ln_b = (const float*)d_in[4];
    const float* stem_w1   = (const float*)d_in[5];
    const float* stem_b1   = (const float*)d_in[6];
    const float* stem_w2   = (const float*)d_in[7];
    const float* stem_b2   = (const float*)d_in[8];
    const float* role_ln_w = (const float*)d_in[9];
    const float* role_ln_b = (const float*)d_in[10];
    const float* Wa        = (const float*)d_in[11];
    const float* Wb        = (const float*)d_in[12];
    const float* Wc        = (const float*)d_in[13];
    const float* class_a   = (const float*)d_in[14];
    const float* class_b   = (const float*)d_in[15];
    const float* class_c   = (const float*)d_in[16];
    const float* query_ln_w= (const float*)d_in[17];
    const float* query_ln_b= (const float*)d_in[18];
    const float* Wq        = (const float*)d_in[19];
    const float* bq        = (const float*)d_in[20];
    float* out = (float*)d_out;

    float *xp, *xnp, *hp, *abcp, *up, *qnp;
    cudaGetSymbolAddress((void**)&xp,   g_x);
    cudaGetSymbolAddress((void**)&xnp,  g_xn);
    cudaGetSymbolAddress((void**)&hp,   g_h);
    cudaGetSymbolAddress((void**)&abcp, g_abc);
    cudaGetSymbolAddress((void**)&up,   g_u);
    cudaGetSymbolAddress((void**)&qnp,  g_qn);

    // 1. embedding
    embed_kernel<<<MM, 128>>>(ids, tok_emb, pos_emb, xp);

    // 2. two stem MLP blocks
    for (int i = 0; i < 2; i++) {
        ln_kernel<<<MM, 128>>>(xp, stem_ln_w + i*DD, stem_ln_b + i*DD, xnp, 1, 0);
        sgemm_kernel<128,128,16,8,8,1><<<dim3(HH/128, MM/128), 256>>>(
            xnp, stem_w1 + (size_t)i*DD*HH, stem_b1 + i*HH, hp, MM, HH, DD, HH, 0);
        sgemm_kernel<128,128,16,8,8,2><<<dim3(DD/128, MM/128), 256>>>(
            hp, stem_w2 + (size_t)i*HH*DD, stem_b2 + i*DD, xp, MM, DD, HH, DD, 0);
    }

    // 3. role LN (over all tokens; last token per batch unused downstream)
    ln_kernel<<<MM, 128>>>(xp, role_ln_w, role_ln_b, xnp, 1, 0);

    // 4. a,b,c = tanh(prefix @ W*)
    sgemm_kernel<64,64,16,4,4,3><<<dim3(1, MM/64), 256>>>(
        xnp, Wa, nullptr, abcp, MM, 64, DD, 192, 0);
    sgemm_kernel<64,64,16,4,4,3><<<dim3(1, MM/64), 256>>>(
        xnp, Wb, nullptr, abcp, MM, 64, DD, 192, 64);
    sgemm_kernel<64,64,16,4,4,3><<<dim3(1, MM/64), 256>>>(
        xnp, Wc, nullptr, abcp, MM, 64, DD, 192, 128);

    // 5. ua/ub/uc = abc @ class^T
    u_kernel<<<dim3(MM/64, 3), 256>>>(abcp, class_a, class_b, class_c, up);

    // 6. query LN (rows b*2048 + 2047)
    ln_kernel<<<BB, 128>>>(xp, query_ln_w, query_ln_b, qnp, LL, LL - 1);

    // 7. exact ordered-triplet scan + query head -> out[8,64]
    scan_kernel<<<BB, CC>>>(up, qnp, Wq, bq, out);
}

// round 2
// speedup vs baseline: 2.2586x; 2.2586x over previous
#include <cuda_runtime.h>
#include <math.h>

#define BB 8
#define LL 2048
#define DD 512
#define HH 1024
#define CC 64
#define MM (BB*LL)   // 16384

// ---------------- scratch (static device globals; no allocations) ----------------
__device__ float g_x  [MM*DD];   // residual stream
__device__ float g_xn [MM*DD];   // LN output
__device__ float g_h  [MM*HH];   // MLP hidden
__device__ float g_abc[MM*192];  // tanh projections a|b|c
__device__ float g_u  [MM*192];  // ua|ub|uc
__device__ float g_qn [BB*DD];   // LN of last token
__device__ float g_w  [DD*192];  // packed Wa|Wb|Wc

__device__ __forceinline__ unsigned f2tf(float f) {
    unsigned u;
    asm("cvt.rna.tf32.f32 %0, %1;" : "=r"(u) : "f"(f));
    return u;
}

// ---------------- embedding ----------------
__global__ void embed_kernel(const int* __restrict__ ids,
                             const float* __restrict__ tok,
                             const float* __restrict__ pos,
                             float* __restrict__ x) {
    int t  = blockIdx.x;
    int id = ids[t];
    int l  = t & (LL - 1);
    float4 a = ((const float4*)(tok + (size_t)id * DD))[threadIdx.x];
    float4 p = ((const float4*)(pos + (size_t)l  * DD))[threadIdx.x];
    float4 o; o.x = a.x + p.x; o.y = a.y + p.y; o.z = a.z + p.z; o.w = a.w + p.w;
    ((float4*)(x + (size_t)t * DD))[threadIdx.x] = o;
}

// ---------------- LayerNorm (D=512, 128 threads/row) ----------------
__global__ void ln_kernel(const float* __restrict__ x,
                          const float* __restrict__ w,
                          const float* __restrict__ b,
                          float* __restrict__ out,
                          int rowMul, int rowOff) {
    __shared__ float red[2][4];
    size_t inRow = (size_t)blockIdx.x * rowMul + rowOff;
    float4 v = ((const float4*)(x + inRow * DD))[threadIdx.x];
    float s  = v.x + v.y + v.z + v.w;
    float s2 = v.x*v.x + v.y*v.y + v.z*v.z + v.w*v.w;
    #pragma unroll
    for (int o = 16; o; o >>= 1) {
        s  += __shfl_down_sync(0xffffffffu, s,  o);
        s2 += __shfl_down_sync(0xffffffffu, s2, o);
    }
    int warp = threadIdx.x >> 5, lane = threadIdx.x & 31;
    if (!lane) { red[0][warp] = s; red[1][warp] = s2; }
    __syncthreads();
    s  = red[0][0] + red[0][1] + red[0][2] + red[0][3];
    s2 = red[1][0] + red[1][1] + red[1][2] + red[1][3];
    float mean = s * (1.0f / DD);
    float var  = s2 * (1.0f / DD) - mean * mean;
    float inv  = rsqrtf(var + 1e-5f);
    int c = threadIdx.x * 4;
    float4 wv = *(const float4*)(w + c);
    float4 bv = *(const float4*)(b + c);
    float4 o;
    o.x = (v.x - mean) * inv * wv.x + bv.x;
    o.y = (v.y - mean) * inv * wv.y + bv.y;
    o.z = (v.z - mean) * inv * wv.z + bv.z;
    o.w = (v.w - mean) * inv * wv.w + bv.w;
    ((float4*)(out + (size_t)blockIdx.x * DD))[threadIdx.x] = o;
}

// ---------------- TF32 tensor-core GEMM ----------------
// C[M,N] = A[M,K] @ B[K,N], fp32 in/out, tf32 mma.sync.m16n8k8.
// 256 threads = 8 warps (4 row x 2 col). Warp tile 32 x (BN/2).
// EPI: 1 bias+exact GELU, 2 bias+residual add, 3 tanh
template<int BM, int BN, int EPI>
__global__ __launch_bounds__(256)
void tf32gemm_kernel(const float* __restrict__ A, const float* __restrict__ Bw,
                     const float* __restrict__ bias, float* __restrict__ Cm,
                     int M, int N, int K, int ldc, int colOff) {
    constexpr int BK = 32;
    constexpr int NI = BN / 16;            // n8 tiles per warp (BN/2 / 8)
    __shared__ float As[BM][BK + 4];       // stride 36: conflict-free frag reads
    __shared__ float Bs[BK][BN + 8];       // stride BN+8: conflict-free frag reads

    const int tid  = threadIdx.x;
    const int lane = tid & 31, warp = tid >> 5;
    const int wr   = warp >> 1, wc = warp & 1;
    const int g    = lane >> 2, tig = lane & 3;
    const int rowBase = blockIdx.y * BM;
    const int colBase = blockIdx.x * BN;

    float acc[2][NI][4];
    #pragma unroll
    for (int mi = 0; mi < 2; mi++)
        #pragma unroll
        for (int ni = 0; ni < NI; ni++)
            #pragma unroll
            for (int r = 0; r < 4; r++) acc[mi][ni][r] = 0.f;

    constexpr int A_IT = (BM * BK / 4) / 256;
    constexpr int B_IT = (BK * BN / 4) / 256;

    for (int k0 = 0; k0 < K; k0 += BK) {
        #pragma unroll
        for (int it = 0; it < A_IT; it++) {
            int idx = tid + it * 256;
            int r = idx / (BK / 4);
            int c = (idx % (BK / 4)) * 4;
            float4 v = *(const float4*)(A + (size_t)(rowBase + r) * K + k0 + c);
            uint4 t; t.x = f2tf(v.x); t.y = f2tf(v.y); t.z = f2tf(v.z); t.w = f2tf(v.w);
            *(uint4*)&As[r][c] = t;
        }
        #pragma unroll
        for (int it = 0; it < B_IT; it++) {
            int idx = tid + it * 256;
            int r = idx / (BN / 4);
            int c = (idx % (BN / 4)) * 4;
            float4 v = *(const float4*)(Bw + (size_t)(k0 + r) * N + colBase + c);
            uint4 t; t.x = f2tf(v.x); t.y = f2tf(v.y); t.z = f2tf(v.z); t.w = f2tf(v.w);
            *(uint4*)&Bs[r][c] = t;
        }
        __syncthreads();

        #pragma unroll
        for (int kk = 0; kk < BK; kk += 8) {
            unsigned af[2][4];
            #pragma unroll
            for (int mi = 0; mi < 2; mi++) {
                int m0 = wr * 32 + mi * 16 + g;
                af[mi][0] = __float_as_uint(As[m0    ][kk + tig    ]);
                af[mi][1] = __float_as_uint(As[m0 + 8][kk + tig    ]);
                af[mi][2] = __float_as_uint(As[m0    ][kk + tig + 4]);
                af[mi][3] = __float_as_uint(As[m0 + 8][kk + tig + 4]);
            }
            unsigned bf[NI][2];
            #pragma unroll
            for (int ni = 0; ni < NI; ni++) {
                int n0 = wc * (BN / 2) + ni * 8 + g;
                bf[ni][0] = __float_as_uint(Bs[kk + tig    ][n0]);
                bf[ni][1] = __float_as_uint(Bs[kk + tig + 4][n0]);
            }
            #pragma unroll
            for (int mi = 0; mi < 2; mi++)
                #pragma unroll
                for (int ni = 0; ni < NI; ni++) {
                    asm volatile(
                        "mma.sync.aligned.m16n8k8.row.col.f32.tf32.tf32.f32 "
                        "{%0,%1,%2,%3}, {%4,%5,%6,%7}, {%8,%9}, {%0,%1,%2,%3};"
                        : "+f"(acc[mi][ni][0]), "+f"(acc[mi][ni][1]),
                          "+f"(acc[mi][ni][2]), "+f"(acc[mi][ni][3])
                        : "r"(af[mi][0]), "r"(af[mi][1]), "r"(af[mi][2]), "r"(af[mi][3]),
                          "r"(bf[ni][0]), "r"(bf[ni][1]));
                }
        }
        __syncthreads();
    }

    // ---------------- epilogue ----------------
    #pragma unroll
    for (int mi = 0; mi < 2; mi++) {
        #pragma unroll
        for (int ni = 0; ni < NI; ni++) {
            int row = rowBase + wr * 32 + mi * 16 + g;
            int col = colBase + wc * (BN / 2) + ni * 8 + tig * 2;
            #pragma unroll
            for (int half = 0; half < 2; half++) {
                int r = row + half * 8;
                float v0 = acc[mi][ni][half * 2 + 0];
                float v1 = acc[mi][ni][half * 2 + 1];
                float2* p = (float2*)(Cm + (size_t)r * ldc + colOff + col);
                if (EPI == 1) {                       // bias + exact GELU
                    v0 += bias[col];  v1 += bias[col + 1];
                    float2 o; o.x = v0 * normcdff(v0); o.y = v1 * normcdff(v1);
                    *p = o;
                } else if (EPI == 2) {                // bias + residual add
                    float2 old = *p;
                    float2 o; o.x = old.x + v0 + bias[col];
                    o.y = old.y + v1 + bias[col + 1];
                    *p = o;
                } else {                               // tanh
                    float2 o; o.x = tanhf(v0); o.y = tanhf(v1);
                    *p = o;
                }
            }
        }
    }
}

// ---------------- pack Wa|Wb|Wc -> [512][192] ----------------
__global__ void pack_w_kernel(const float* __restrict__ Wa,
                              const float* __restrict__ Wb,
                              const float* __restrict__ Wc,
                              float* __restrict__ W) {
    int i = blockIdx.x * 256 + threadIdx.x;      // 0 .. 512*64-1
    if (i < DD * 64) {
        int r = i >> 6, c = i & 63;
        W[r * 192 + c]       = Wa[i];
        W[r * 192 + 64 + c]  = Wb[i];
        W[r * 192 + 128 + c] = Wc[i];
    }
}

// ---------------- u = abc @ class^T ----------------
__global__ void u_kernel(const float* __restrict__ abc,
                         const float* __restrict__ cA,
                         const float* __restrict__ cB,
                         const float* __restrict__ cC,
                         float* __restrict__ u) {
    int g = blockIdx.y;
    const float* cls = (g == 0) ? cA : (g == 1) ? cB : cC;
    __shared__ float Ct[64][65];
    __shared__ float At[64][65];
    int tid = threadIdx.x;
    int t0  = blockIdx.x * 64;
    for (int i = tid; i < 4096; i += 256) Ct[i >> 6][i & 63] = cls[i];
    for (int i = tid; i < 4096; i += 256) {
        int tok = i >> 6, r = i & 63;
        At[tok][r] = abc[(size_t)(t0 + tok) * 192 + g * 64 + r];
    }
    __syncthreads();
    int tx = tid & 15, ty = tid >> 4;
    float acc[4][4];
    #pragma unroll
    for (int i = 0; i < 4; i++)
        #pragma unroll
        for (int j = 0; j < 4; j++) acc[i][j] = 0.f;
    for (int r = 0; r < 64; r++) {
        float a[4], b[4];
        #pragma unroll
        for (int i = 0; i < 4; i++) a[i] = At[ty*4 + i][r];
        #pragma unroll
        for (int j = 0; j < 4; j++) b[j] = Ct[tx*4 + j][r];
        #pragma unroll
        for (int i = 0; i < 4; i++)
            #pragma unroll
            for (int j = 0; j < 4; j++) acc[i][j] = fmaf(a[i], b[j], acc[i][j]);
    }
    #pragma unroll
    for (int i = 0; i < 4; i++)
        #pragma unroll
        for (int j = 0; j < 4; j++)
            u[(size_t)(t0 + ty*4 + i) * 192 + g * 64 + tx*4 + j] = acc[i][j];
}

// ---------------- triplet scan + query head ----------------
__global__ void scan_kernel(const float* __restrict__ u,
                            const float* __restrict__ qn,
                            const float* __restrict__ Wq,
                            const float* __restrict__ bq,
                            float* __restrict__ out) {
    int b = blockIdx.x;
    int c = threadIdx.x;
    const float* base = u + (size_t)b * LL * 192;
    float prefA = 0.f, prefT = 0.f, s = 0.f;
    #pragma unroll 4
    for (int l = 0; l < LL - 1; l++) {
        const float* p = base + (size_t)l * 192;
        float va = p[c], vb = p[64 + c], vc = p[128 + c];
        s     = fmaf(vc, prefT, s);
        prefT = fmaf(vb, prefA, prefT);
        prefA += va;
    }
    float q = 0.f;
    const float* qr = qn + b * DD;
    #pragma unroll 8
    for (int k = 0; k < DD; k++) q = fmaf(qr[k], Wq[k * CC + c], q);
    const float inv_den = (float)(6.0 / (2047.0 * 2046.0 * 2045.0));
    out[b * CC + c] = s * inv_den + q + bq[c];
}

// ---------------- launch ----------------
extern "C" void kernel_launch(void* const* d_in, const int* in_sizes, int n_in,
                              void* d_out, int out_size) {
    const int*   ids       = (const int*)  d_in[0];
    const float* tok_emb   = (const float*)d_in[1];
    const float* pos_emb   = (const float*)d_in[2];
    const float* stem_ln_w = (const float*)d_in[3];
    const float* stem_ln_b = (const float*)d_in[4];
    const float* stem_w1   = (const float*)d_in[5];
    const float* stem_b1   = (const float*)d_in[6];
    const float* stem_w2   = (const float*)d_in[7];
    const float* stem_b2   = (const float*)d_in[8];
    const float* role_ln_w = (const float*)d_in[9];
    const float* role_ln_b = (const float*)d_in[10];
    const float* Wa        = (const float*)d_in[11];
    const float* Wb        = (const float*)d_in[12];
    const float* Wc        = (const float*)d_in[13];
    const float* class_a   = (const float*)d_in[14];
    const float* class_b   = (const float*)d_in[15];
    const float* class_c   = (const float*)d_in[16];
    const float* query_ln_w= (const float*)d_in[17];
    const float* query_ln_b= (const float*)d_in[18];
    const float* Wq        = (const float*)d_in[19];
    const float* bq        = (const float*)d_in[20];
    float* out = (float*)d_out;

    float *xp, *xnp, *hp, *abcp, *up, *qnp, *wp;
    cudaGetSymbolAddress((void**)&xp,   g_x);
    cudaGetSymbolAddress((void**)&xnp,  g_xn);
    cudaGetSymbolAddress((void**)&hp,   g_h);
    cudaGetSymbolAddress((void**)&abcp, g_abc);
    cudaGetSymbolAddress((void**)&up,   g_u);
    cudaGetSymbolAddress((void**)&qnp,  g_qn);
    cudaGetSymbolAddress((void**)&wp,   g_w);

    // 1. embedding
    embed_kernel<<<MM, 128>>>(ids, tok_emb, pos_emb, xp);

    // 2. two stem MLP blocks (tf32 tensor cores)
    for (int i = 0; i < 2; i++) {
        ln_kernel<<<MM, 128>>>(xp, stem_ln_w + i*DD, stem_ln_b + i*DD, xnp, 1, 0);
        tf32gemm_kernel<128,128,1><<<dim3(HH/128, MM/128), 256>>>(
            xnp, stem_w1 + (size_t)i*DD*HH, stem_b1 + i*HH, hp, MM, HH, DD, HH, 0);
        tf32gemm_kernel<128,128,2><<<dim3(DD/128, MM/128), 256>>>(
            hp, stem_w2 + (size_t)i*HH*DD, stem_b2 + i*DD, xp, MM, DD, HH, DD, 0);
    }

    // 3. role LN
    ln_kernel<<<MM, 128>>>(xp, role_ln_w, role_ln_b, xnp, 1, 0);

    // 4. packed tanh projections: abc = tanh(xn @ [Wa|Wb|Wc])
    pack_w_kernel<<<(DD*64 + 255)/256, 256>>>(Wa, Wb, Wc, wp);
    tf32gemm_kernel<128,64,3><<<dim3(3, MM/128), 256>>>(
        xnp, wp, nullptr, abcp, MM, 192, DD, 192, 0);

    // 5. ua/ub/uc = abc @ class^T
    u_kernel<<<dim3(MM/64, 3), 256>>>(abcp, class_a, class_b, class_c, up);

    // 6. query LN (rows b*2048 + 2047)
    ln_kernel<<<BB, 128>>>(xp, query_ln_w, query_ln_b, qnp, LL, LL - 1);

    // 7. triplet scan + query head
    scan_kernel<<<BB, CC>>>(up, qnp, Wq, bq, out);
}

// round 3
// speedup vs baseline: 2.8736x; 1.2723x over previous
#include <cuda_runtime.h>
#include <math.h>

#define BB 8
#define LL 2048
#define DD 512
#define HH 1024
#define CC 64
#define MM (BB*LL)   // 16384
#define NSEG 32
#define SEGL 64

// ---------------- scratch (static device globals; no allocations) ----------------
__device__ float g_x  [MM*DD];
__device__ float g_xn [MM*DD];
__device__ float g_h  [MM*HH];
__device__ float g_abc[MM*192];
__device__ float g_u  [MM*192];
__device__ float g_qn [BB*DD];
__device__ float g_w  [DD*192];
__device__ float g_seg[BB*NSEG*6*64];

__device__ __forceinline__ unsigned f2tf(float f) {
    unsigned u;
    asm("cvt.rna.tf32.f32 %0, %1;" : "=r"(u) : "f"(f));
    return u;
}
__device__ __forceinline__ void cp16(void* dst, const void* src) {
    unsigned d = (unsigned)__cvta_generic_to_shared(dst);
    asm volatile("cp.async.cg.shared.global [%0], [%1], 16;\n" :: "r"(d), "l"(src));
}
__device__ __forceinline__ void cp_commit() {
    asm volatile("cp.async.commit_group;\n");
}
template<int N>
__device__ __forceinline__ void cp_wait() {
    asm volatile("cp.async.wait_group %0;\n" :: "n"(N));
}

// ---------------- embedding ----------------
__global__ void embed_kernel(const int* __restrict__ ids,
                             const float* __restrict__ tok,
                             const float* __restrict__ pos,
                             float* __restrict__ x) {
    int t  = blockIdx.x;
    int id = ids[t];
    int l  = t & (LL - 1);
    float4 a = ((const float4*)(tok + (size_t)id * DD))[threadIdx.x];
    float4 p = ((const float4*)(pos + (size_t)l  * DD))[threadIdx.x];
    float4 o; o.x = a.x + p.x; o.y = a.y + p.y; o.z = a.z + p.z; o.w = a.w + p.w;
    ((float4*)(x + (size_t)t * DD))[threadIdx.x] = o;
}

// ---------------- LayerNorm ----------------
__global__ void ln_kernel(const float* __restrict__ x,
                          const float* __restrict__ w,
                          const float* __restrict__ b,
                          float* __restrict__ out,
                          int rowMul, int rowOff) {
    __shared__ float red[2][4];
    size_t inRow = (size_t)blockIdx.x * rowMul + rowOff;
    float4 v = ((const float4*)(x + inRow * DD))[threadIdx.x];
    float s  = v.x + v.y + v.z + v.w;
    float s2 = v.x*v.x + v.y*v.y + v.z*v.z + v.w*v.w;
    #pragma unroll
    for (int o = 16; o; o >>= 1) {
        s  += __shfl_down_sync(0xffffffffu, s,  o);
        s2 += __shfl_down_sync(0xffffffffu, s2, o);
    }
    int warp = threadIdx.x >> 5, lane = threadIdx.x & 31;
    if (!lane) { red[0][warp] = s; red[1][warp] = s2; }
    __syncthreads();
    s  = red[0][0] + red[0][1] + red[0][2] + red[0][3];
    s2 = red[1][0] + red[1][1] + red[1][2] + red[1][3];
    float mean = s * (1.0f / DD);
    float var  = s2 * (1.0f / DD) - mean * mean;
    float inv  = rsqrtf(var + 1e-5f);
    int c = threadIdx.x * 4;
    float4 wv = *(const float4*)(w + c);
    float4 bv = *(const float4*)(b + c);
    float4 o;
    o.x = (v.x - mean) * inv * wv.x + bv.x;
    o.y = (v.y - mean) * inv * wv.y + bv.y;
    o.z = (v.z - mean) * inv * wv.z + bv.z;
    o.w = (v.w - mean) * inv * wv.w + bv.w;
    ((float4*)(out + (size_t)blockIdx.x * DD))[threadIdx.x] = o;
}

// ---------------- TF32 tensor-core GEMM, cp.async 2-stage pipeline ----------------
// EPI: 1 bias+exact GELU, 2 bias+residual add, 3 tanh
template<int BM, int BN, int EPI>
__global__ __launch_bounds__(256)
void tf32gemm_async(const float* __restrict__ A, const float* __restrict__ Bw,
                    const float* __restrict__ bias, float* __restrict__ Cm,
                    int M, int N, int K, int ldc, int colOff) {
    constexpr int BK = 32;
    constexpr int AP = BK + 4;                 // A smem row stride (floats), 16B-mult
    constexpr int BP = BN + 8;                 // B smem row stride, conflict-free
    constexpr int NI = BN / 16;

    extern __shared__ float sm[];
    float (*As)[BM][AP] = (float (*)[BM][AP])sm;
    float (*Bs)[BK][BP] = (float (*)[BK][BP])(sm + 2 * BM * AP);

    const int tid  = threadIdx.x;
    const int lane = tid & 31, warp = tid >> 5;
    const int wr   = warp >> 1, wc = warp & 1;
    const int g    = lane >> 2, tig = lane & 3;
    const int rowBase = blockIdx.y * BM;
    const int colBase = blockIdx.x * BN;

    float acc[2][NI][4];
    #pragma unroll
    for (int mi = 0; mi < 2; mi++)
        #pragma unroll
        for (int ni = 0; ni < NI; ni++)
            #pragma unroll
            for (int r = 0; r < 4; r++) acc[mi][ni][r] = 0.f;

    constexpr int A_IT = (BM * BK / 4) / 256;
    constexpr int B_IT = (BK * BN / 4) / 256;
    const int nt = K / BK;

    auto issue = [&](int kt) {
        int st = kt & 1;
        int k0 = kt * BK;
        #pragma unroll
        for (int it = 0; it < A_IT; it++) {
            int idx = tid + it * 256;
            int r = idx / (BK / 4);
            int c = (idx % (BK / 4)) * 4;
            cp16(&As[st][r][c], A + (size_t)(rowBase + r) * K + k0 + c);
        }
        #pragma unroll
        for (int it = 0; it < B_IT; it++) {
            int idx = tid + it * 256;
            int r = idx / (BN / 4);
            int c = (idx % (BN / 4)) * 4;
            cp16(&Bs[st][r][c], Bw + (size_t)(k0 + r) * N + colBase + c);
        }
    };

    issue(0);
    cp_commit();

    for (int kt = 0; kt < nt; kt++) {
        if (kt + 1 < nt) { issue(kt + 1); cp_commit(); cp_wait<1>(); }
        else            { cp_commit(); cp_wait<0>(); }
        __syncthreads();

        int st = kt & 1;
        #pragma unroll
        for (int kk = 0; kk < BK; kk += 8) {
            unsigned af[2][4];
            #pragma unroll
            for (int mi = 0; mi < 2; mi++) {
                int m0 = wr * 32 + mi * 16 + g;
                af[mi][0] = f2tf(As[st][m0    ][kk + tig    ]);
                af[mi][1] = f2tf(As[st][m0 + 8][kk + tig    ]);
                af[mi][2] = f2tf(As[st][m0    ][kk + tig + 4]);
                af[mi][3] = f2tf(As[st][m0 + 8][kk + tig + 4]);
            }
            unsigned bf[NI][2];
            #pragma unroll
            for (int ni = 0; ni < NI; ni++) {
                int n0 = wc * (BN / 2) + ni * 8 + g;
                bf[ni][0] = f2tf(Bs[st][kk + tig    ][n0]);
                bf[ni][1] = f2tf(Bs[st][kk + tig + 4][n0]);
            }
            #pragma unroll
            for (int mi = 0; mi < 2; mi++)
                #pragma unroll
                for (int ni = 0; ni < NI; ni++) {
                    asm volatile(
                        "mma.sync.aligned.m16n8k8.row.col.f32.tf32.tf32.f32 "
                        "{%0,%1,%2,%3}, {%4,%5,%6,%7}, {%8,%9}, {%0,%1,%2,%3};"
                        : "+f"(acc[mi][ni][0]), "+f"(acc[mi][ni][1]),
                          "+f"(acc[mi][ni][2]), "+f"(acc[mi][ni][3])
                        : "r"(af[mi][0]), "r"(af[mi][1]), "r"(af[mi][2]), "r"(af[mi][3]),
                          "r"(bf[ni][0]), "r"(bf[ni][1]));
                }
        }
        __syncthreads();
    }

    #pragma unroll
    for (int mi = 0; mi < 2; mi++) {
        #pragma unroll
        for (int ni = 0; ni < NI; ni++) {
            int row = rowBase + wr * 32 + mi * 16 + g;
            int col = colBase + wc * (BN / 2) + ni * 8 + tig * 2;
            #pragma unroll
            for (int half = 0; half < 2; half++) {
                int r = row + half * 8;
                float v0 = acc[mi][ni][half * 2 + 0];
                float v1 = acc[mi][ni][half * 2 + 1];
                float2* p = (float2*)(Cm + (size_t)r * ldc + colOff + col);
                if (EPI == 1) {
                    v0 += bias[col];  v1 += bias[col + 1];
                    float2 o; o.x = v0 * normcdff(v0); o.y = v1 * normcdff(v1);
                    *p = o;
                } else if (EPI == 2) {
                    float2 old = *p;
                    float2 o; o.x = old.x + v0 + bias[col];
                    o.y = old.y + v1 + bias[col + 1];
                    *p = o;
                } else {
                    float2 o; o.x = tanhf(v0); o.y = tanhf(v1);
                    *p = o;
                }
            }
        }
    }
}

// ---------------- pack Wa|Wb|Wc -> [512][192] ----------------
__global__ void pack_w_kernel(const float* __restrict__ Wa,
                              const float* __restrict__ Wb,
                              const float* __restrict__ Wc,
                              float* __restrict__ W) {
    int i = blockIdx.x * 256 + threadIdx.x;
    if (i < DD * 64) {
        int r = i >> 6, c = i & 63;
        W[r * 192 + c]       = Wa[i];
        W[r * 192 + 64 + c]  = Wb[i];
        W[r * 192 + 128 + c] = Wc[i];
    }
}

// ---------------- u = abc @ class^T ----------------
__global__ void u_kernel(const float* __restrict__ abc,
                         const float* __restrict__ cA,
                         const float* __restrict__ cB,
                         const float* __restrict__ cC,
                         float* __restrict__ u) {
    int g = blockIdx.y;
    const float* cls = (g == 0) ? cA : (g == 1) ? cB : cC;
    __shared__ float Ct[64][65];
    __shared__ float At[64][65];
    int tid = threadIdx.x;
    int t0  = blockIdx.x * 64;
    for (int i = tid; i < 4096; i += 256) Ct[i >> 6][i & 63] = cls[i];
    for (int i = tid; i < 4096; i += 256) {
        int tok = i >> 6, r = i & 63;
        At[tok][r] = abc[(size_t)(t0 + tok) * 192 + g * 64 + r];
    }
    __syncthreads();
    int tx = tid & 15, ty = tid >> 4;
    float acc[4][4];
    #pragma unroll
    for (int i = 0; i < 4; i++)
        #pragma unroll
        for (int j = 0; j < 4; j++) acc[i][j] = 0.f;
    for (int r = 0; r < 64; r++) {
        float a[4], b[4];
        #pragma unroll
        for (int i = 0; i < 4; i++) a[i] = At[ty*4 + i][r];
        #pragma unroll
        for (int j = 0; j < 4; j++) b[j] = Ct[tx*4 + j][r];
        #pragma unroll
        for (int i = 0; i < 4; i++)
            #pragma unroll
            for (int j = 0; j < 4; j++) acc[i][j] = fmaf(a[i], b[j], acc[i][j]);
    }
    #pragma unroll
    for (int i = 0; i < 4; i++)
        #pragma unroll
        for (int j = 0; j < 4; j++)
            u[(size_t)(t0 + ty*4 + i) * 192 + g * 64 + tx*4 + j] = acc[i][j];
}

// ---------------- parallel triplet scan: phase 1 (per-segment aggregates) ----------------
__global__ void scan_seg_kernel(const float* __restrict__ u,
                                float* __restrict__ segout) {
    int b = blockIdx.x, s = blockIdx.y, c = threadIdx.x;
    int l0 = s * SEGL;
    int l1 = min(l0 + SEGL, LL - 1);
    const float* p = u + ((size_t)b * LL + l0) * 192;
    float pA = 0.f, pB = 0.f, pT = 0.f, AB = 0.f, BC = 0.f, S = 0.f, Cs = 0.f;
    #pragma unroll 4
    for (int l = l0; l < l1; l++) {
        float va = p[c], vb = p[64 + c], vc = p[128 + c];
        p += 192;
        S  = fmaf(vc, pT, S);
        BC = fmaf(vc, pB, BC);
        pT = fmaf(vb, pA, pT);
        AB = fmaf(vb, pA, AB);
        pB += vb;
        pA += va;
        Cs += vc;
    }
    float* o = segout + ((size_t)(b * NSEG + s) * 6) * 64 + c;
    o[0]   = pA;  o[64]  = pB;  o[128] = Cs;
    o[192] = AB;  o[256] = BC;  o[320] = S;
}

// ---------------- phase 2: combine segments + query head ----------------
__global__ void scan_combine_kernel(const float* __restrict__ segout,
                                    const float* __restrict__ qn,
                                    const float* __restrict__ Wq,
                                    const float* __restrict__ bq,
                                    float* __restrict__ out) {
    int b = blockIdx.x, c = threadIdx.x;
    float PA = 0.f, PAB = 0.f, PE = 0.f, total = 0.f;
    #pragma unroll
    for (int s = 0; s < NSEG; s++) {
        const float* o = segout + ((size_t)(b * NSEG + s) * 6) * 64 + c;
        float A = o[0], B = o[64], C = o[128], AB = o[192], BC = o[256], S = o[320];
        total += S + C * (PE + PAB) + BC * PA;
        PE  = fmaf(B, PA, PE);
        PAB += AB;
        PA  += A;
    }
    float q = 0.f;
    const float* qr = qn + b * DD;
    #pragma unroll 8
    for (int k = 0; k < DD; k++) q = fmaf(qr[k], Wq[k * CC + c], q);
    const float inv_den = (float)(6.0 / (2047.0 * 2046.0 * 2045.0));
    out[b * CC + c] = total * inv_den + q + bq[c];
}

// ---------------- launch ----------------
extern "C" void kernel_launch(void* const* d_in, const int* in_sizes, int n_in,
                              void* d_out, int out_size) {
    const int*   ids       = (const int*)  d_in[0];
    const float* tok_emb   = (const float*)d_in[1];
    const float* pos_emb   = (const float*)d_in[2];
    const float* stem_ln_w = (const float*)d_in[3];
    const float* stem_ln_b = (const float*)d_in[4];
    const float* stem_w1   = (const float*)d_in[5];
    const float* stem_b1   = (const float*)d_in[6];
    const float* stem_w2   = (const float*)d_in[7];
    const float* stem_b2   = (const float*)d_in[8];
    const float* role_ln_w = (const float*)d_in[9];
    const float* role_ln_b = (const float*)d_in[10];
    const float* Wa        = (const float*)d_in[11];
    const float* Wb        = (const float*)d_in[12];
    const float* Wc        = (const float*)d_in[13];
    const float* class_a   = (const float*)d_in[14];
    const float* class_b   = (const float*)d_in[15];
    const float* class_c   = (const float*)d_in[16];
    const float* query_ln_w= (const float*)d_in[17];
    const float* query_ln_b= (const float*)d_in[18];
    const float* Wq        = (const float*)d_in[19];
    const float* bq        = (const float*)d_in[20];
    float* out = (float*)d_out;

    float *xp, *xnp, *hp, *abcp, *up, *qnp, *wp, *segp;
    cudaGetSymbolAddress((void**)&xp,   g_x);
    cudaGetSymbolAddress((void**)&xnp,  g_xn);
    cudaGetSymbolAddress((void**)&hp,   g_h);
    cudaGetSymbolAddress((void**)&abcp, g_abc);
    cudaGetSymbolAddress((void**)&up,   g_u);
    cudaGetSymbolAddress((void**)&qnp,  g_qn);
    cudaGetSymbolAddress((void**)&wp,   g_w);
    cudaGetSymbolAddress((void**)&segp, g_seg);

    // dynamic smem sizes
    constexpr int SM128 = (2 * 128 * 36 + 2 * 32 * 136) * 4;  // 71680
    constexpr int SM64  = (2 * 128 * 36 + 2 * 32 * 72)  * 4;  // 55296
    cudaFuncSetAttribute(tf32gemm_async<128,128,1>,
                         cudaFuncAttributeMaxDynamicSharedMemorySize, SM128);
    cudaFuncSetAttribute(tf32gemm_async<128,128,2>,
                         cudaFuncAttributeMaxDynamicSharedMemorySize, SM128);
    cudaFuncSetAttribute(tf32gemm_async<128,64,3>,
                         cudaFuncAttributeMaxDynamicSharedMemorySize, SM64);

    // 1. embedding
    embed_kernel<<<MM, 128>>>(ids, tok_emb, pos_emb, xp);

    // 2. two stem MLP blocks
    for (int i = 0; i < 2; i++) {
        ln_kernel<<<MM, 128>>>(xp, stem_ln_w + i*DD, stem_ln_b + i*DD, xnp, 1, 0);
        tf32gemm_async<128,128,1><<<dim3(HH/128, MM/128), 256, SM128>>>(
            xnp, stem_w1 + (size_t)i*DD*HH, stem_b1 + i*HH, hp, MM, HH, DD, HH, 0);
        tf32gemm_async<128,128,2><<<dim3(DD/128, MM/128), 256, SM128>>>(
            hp, stem_w2 + (size_t)i*HH*DD, stem_b2 + i*DD, xp, MM, DD, HH, DD, 0);
    }

    // 3. role LN
    ln_kernel<<<MM, 128>>>(xp, role_ln_w, role_ln_b, xnp, 1, 0);

    // 4. packed tanh projections
    pack_w_kernel<<<(DD*64 + 255)/256, 256>>>(Wa, Wb, Wc, wp);
    tf32gemm_async<128,64,3><<<dim3(3, MM/128), 256, SM64>>>(
        xnp, wp, nullptr, abcp, MM, 192, DD, 192, 0);

    // 5. ua/ub/uc = abc @ class^T
    u_kernel<<<dim3(MM/64, 3), 256>>>(abcp, class_a, class_b, class_c, up);

    // 6. query LN
    ln_kernel<<<BB, 128>>>(xp, query_ln_w, query_ln_b, qnp, LL, LL - 1);

    // 7. parallel triplet scan + combine
    scan_seg_kernel<<<dim3(BB, NSEG), 64>>>(up, segp);
    scan_combine_kernel<<<BB, CC>>>(segp, qnp, Wq, bq, out);
}